// round 12
// baseline (speedup 1.0000x reference)
#include <cuda_runtime.h>

#define NN      10000
#define NE      160000
#define NR      4
#define NG      256
#define F3      712
#define NBUCK   (NN * NR)
#define NSCANB  ((NBUCK + 255) / 256)

// ---------------- static device scratch (no allocations allowed) ----------------
__device__ float g_AX[(size_t)NN * 4 * 1024];   // aggregated operand [N, 4*D], tf32-rounded
__device__ float g_h1[(size_t)NN * 1024];       // layer1 out; reused for layer3 out
__device__ float g_h2[(size_t)NN * 1024];       // layer2 out
__device__ float g_xr[(size_t)NN * 64];         // tf32-rounded input x
__device__ float g_B1[320 * 1024];              // stacked [W1|root1], tf32-rounded
__device__ float g_B2[(size_t)5120 * 1024];     // stacked [W2|root2], tf32-rounded
__device__ float g_B3[(size_t)5120 * 712];      // stacked [W3|root3], tf32-rounded
__device__ int   g_cnt[NBUCK];
__device__ int   g_off[NBUCK];
__device__ int   g_cur[NBUCK];
__device__ int   g_bsum[NSCANB + 1];
__device__ int   g_es[NE];
__device__ float g_pool[NG * F3];
__device__ float g_pcnt[NG];

__device__ __forceinline__ unsigned rn_tf32(float x) {
    unsigned r;
    asm("cvt.rna.tf32.f32 %0, %1;" : "=r"(r) : "f"(x));
    return r;
}
__device__ __forceinline__ float rn_tf32f(float x) {
    return __uint_as_float(rn_tf32(x));
}

// ---------------- weight pre-conversion: dst = rn_tf32([W | root]) ----------------
__global__ void k_wconv(const float* __restrict__ W, const float* __restrict__ root,
                        float* __restrict__ dst, long nW, long nTot) {
    long i = ((long)blockIdx.x * blockDim.x + threadIdx.x) * 4;
    if (i >= nTot) return;
    float4 v = (i < nW) ? *(const float4*)(W + i) : *(const float4*)(root + (i - nW));
    v.x = rn_tf32f(v.x); v.y = rn_tf32f(v.y); v.z = rn_tf32f(v.z); v.w = rn_tf32f(v.w);
    *(float4*)(dst + i) = v;
}
__global__ void k_xconv(const float* __restrict__ x) {
    long i = ((long)blockIdx.x * blockDim.x + threadIdx.x) * 4;
    if (i >= (long)NN * 64) return;
    float4 v = *(const float4*)(x + i);
    v.x = rn_tf32f(v.x); v.y = rn_tf32f(v.y); v.z = rn_tf32f(v.z); v.w = rn_tf32f(v.w);
    *(float4*)(g_xr + i) = v;
}

// ---------------- CSR build ----------------
__global__ void k_zero_cnt() {
    int i = blockIdx.x * blockDim.x + threadIdx.x;
    if (i < NBUCK) g_cnt[i] = 0;
}
__global__ void k_count(const int* __restrict__ dst, const int* __restrict__ et) {
    int i = blockIdx.x * blockDim.x + threadIdx.x;
    if (i < NE) atomicAdd(&g_cnt[dst[i] * NR + et[i]], 1);
}
__global__ void k_scanA() {
    __shared__ int sd[256];
    int t = threadIdx.x;
    int i = blockIdx.x * 256 + t;
    int v = (i < NBUCK) ? g_cnt[i] : 0;
    sd[t] = v;
    __syncthreads();
#pragma unroll
    for (int o = 1; o < 256; o <<= 1) {
        int u = (t >= o) ? sd[t - o] : 0;
        __syncthreads();
        sd[t] += u;
        __syncthreads();
    }
    if (i < NBUCK) g_off[i] = sd[t] - v;
    if (t == 255) g_bsum[blockIdx.x] = sd[t];
}
__global__ void k_scanB() {
    if (threadIdx.x == 0) {
        int run = 0;
        for (int b = 0; b < NSCANB; b++) { int s = g_bsum[b]; g_bsum[b] = run; run += s; }
    }
}
__global__ void k_scanC() {
    int i = blockIdx.x * blockDim.x + threadIdx.x;
    if (i < NBUCK) {
        int o = g_off[i] + g_bsum[i >> 8];
        g_off[i] = o;
        g_cur[i] = o;
    }
}
__global__ void k_scatter(const int* __restrict__ src, const int* __restrict__ dst,
                          const int* __restrict__ et) {
    int e = blockIdx.x * blockDim.x + threadIdx.x;
    if (e < NE) {
        int b = dst[e] * NR + et[e];
        int pos = atomicAdd(&g_cur[b], 1);
        g_es[pos] = src[e];
    }
}

// ---------------- CSR aggregation (tf32-rounded output) ----------------
__global__ void k_aggcsr(const float* __restrict__ x0, int sel, int D) {
    int per = D >> 2;
    int npb = 256 / per;
    int local = threadIdx.x / per;
    int j = threadIdx.x - local * per;
    int n = blockIdx.x * npb + local;
    if (n >= NN) return;
    const float* x = (sel == 0) ? x0 : (sel == 1 ? g_h1 : g_h2);
    const float4* x4 = (const float4*)x;
    float4* out4 = (float4*)g_AX;
    size_t obase = (size_t)n * (NR * per);
#pragma unroll
    for (int r = 0; r < NR; r++) {
        int b = n * NR + r;
        int start = g_off[b];
        int cnt = g_cnt[b];
        float4 acc = make_float4(0.f, 0.f, 0.f, 0.f);
        for (int e = 0; e < cnt; e++) {
            int s = g_es[start + e];
            float4 v = x4[(size_t)s * per + j];
            acc.x += v.x; acc.y += v.y; acc.z += v.z; acc.w += v.w;
        }
        float inv = 1.f / fmaxf((float)cnt, 1.f);
        acc.x = rn_tf32f(acc.x * inv);
        acc.y = rn_tf32f(acc.y * inv);
        acc.z = rn_tf32f(acc.z * inv);
        acc.w = rn_tf32f(acc.w * inv);
        out4[obase + r * per + j] = acc;
    }
}

// ---------------- tf32 mma.sync stacked GEMM (pre-rounded) + bias + relu ----------
// CTA: 128M x 128N, BK=32, 8 warps of 64x32. 3-stage cp.async pipeline (dist 2).
// __launch_bounds__(256, 2) -> <=128 regs -> 2 CTAs/SM (regs + smem both fit).
// Logical A row n = [ g_AX[n, 0..4D) | H[n, 0..D) ], K = 5D, Kw = 4D. All pre-rounded.
// B = stacked pre-rounded [W|root], row-major [K, F].
#define AS_STRIDE 36
#define BS_STRIDE 132
#define ASZ (128 * AS_STRIDE)       // 4608 floats
#define BSZ (32 * BS_STRIDE)        // 4224 floats
#define NSTAGE 3
#define SM_TOTAL_B (NSTAGE * (ASZ + BSZ) * 4)   // 105984 bytes; x2 CTA = 207KB <= 228KB

__device__ __forceinline__ void cp_async16(unsigned dst, const float* src, int sz) {
    asm volatile("cp.async.ca.shared.global [%0], [%1], 16, %2;"
                 :: "r"(dst), "l"(src), "r"(sz));
}
__device__ __forceinline__ void cp_commit() {
    asm volatile("cp.async.commit_group;" ::: "memory");
}

__global__ __launch_bounds__(256, 2)
void k_gemm_mma(const float* __restrict__ Bmat, const float* __restrict__ bias,
                const float* __restrict__ Hin,
                int M, int D, int F, int osel, int do_round) {
    extern __shared__ float sm[];
    const float* H = Hin;
    float* out = (osel == 1) ? g_h1 : g_h2;
    int K = 5 * D, Kw = 4 * D;

    int t = threadIdx.x, lane = t & 31, wid = t >> 5;
    int row0 = blockIdx.y * 128, col0 = blockIdx.x * 128;
    int m0w = (wid >> 2) * 64, n0w = (wid & 3) * 32;
    int g = lane >> 2, tg = lane & 3;
    int nch = K >> 5;

    float c[4][4][4];
#pragma unroll
    for (int i = 0; i < 4; i++)
#pragma unroll
        for (int j = 0; j < 4; j++)
#pragma unroll
            for (int k = 0; k < 4; k++) c[i][j][k] = 0.f;

    unsigned smb = (unsigned)__cvta_generic_to_shared(sm);

    auto load_chunk = [&](int ch, int buf) {
        unsigned as_b = smb + (unsigned)buf * ASZ * 4;
#pragma unroll
        for (int l = 0; l < 4; l++) {
            int id = t + (l << 8);
            int m = id >> 3, k4 = id & 7;
            int row = row0 + m;
            int krow = (ch << 5) + (k4 << 2);
            const float* src = (krow < Kw) ? (g_AX + (size_t)row * Kw + krow)
                                           : (H + (size_t)row * D + (krow - Kw));
            cp_async16(as_b + (unsigned)(m * AS_STRIDE + k4 * 4) * 4, src, (row < M) ? 16 : 0);
        }
        unsigned bs_b = smb + (unsigned)(NSTAGE * ASZ + buf * BSZ) * 4;
#pragma unroll
        for (int l = 0; l < 4; l++) {
            int id = t + (l << 8);
            int k = id >> 5, n4 = id & 31;
            int krow = (ch << 5) + k;
            int col = col0 + (n4 << 2);
            cp_async16(bs_b + (unsigned)(k * BS_STRIDE + n4 * 4) * 4,
                       Bmat + (size_t)krow * F + col, (col < F) ? 16 : 0);
        }
        cp_commit();
    };

    // prologue: fill 2 stages
    load_chunk(0, 0);
    if (nch > 1) load_chunk(1, 1);

    int buf = 0;
    for (int ch = 0; ch < nch; ch++) {
        if (ch + 2 < nch) load_chunk(ch + 2, (ch + 2) % NSTAGE);

        int rem = nch - 1 - ch;
        if (rem >= 2)      asm volatile("cp.async.wait_group 2;" ::: "memory");
        else if (rem == 1) asm volatile("cp.async.wait_group 1;" ::: "memory");
        else               asm volatile("cp.async.wait_group 0;" ::: "memory");
        __syncthreads();

        const float* As = sm + buf * ASZ;
        const float* Bs = sm + NSTAGE * ASZ + buf * BSZ;

#pragma unroll
        for (int kk = 0; kk < 32; kk += 8) {
            unsigned b[4][2];
#pragma unroll
            for (int nt = 0; nt < 4; nt++) {
                int n = n0w + nt * 8 + g;
                b[nt][0] = __float_as_uint(Bs[(kk + tg) * BS_STRIDE + n]);
                b[nt][1] = __float_as_uint(Bs[(kk + 4 + tg) * BS_STRIDE + n]);
            }
#pragma unroll
            for (int mt = 0; mt < 4; mt++) {
                int m = m0w + mt * 16 + g;
                unsigned a[4];
                a[0] = __float_as_uint(As[m * AS_STRIDE + kk + tg]);
                a[1] = __float_as_uint(As[(m + 8) * AS_STRIDE + kk + tg]);
                a[2] = __float_as_uint(As[m * AS_STRIDE + kk + 4 + tg]);
                a[3] = __float_as_uint(As[(m + 8) * AS_STRIDE + kk + 4 + tg]);
#pragma unroll
                for (int nt = 0; nt < 4; nt++)
                    asm volatile(
                        "mma.sync.aligned.m16n8k8.row.col.f32.tf32.tf32.f32 "
                        "{%0,%1,%2,%3},{%4,%5,%6,%7},{%8,%9},{%0,%1,%2,%3};"
                        : "+f"(c[mt][nt][0]), "+f"(c[mt][nt][1]),
                          "+f"(c[mt][nt][2]), "+f"(c[mt][nt][3])
                        : "r"(a[0]), "r"(a[1]), "r"(a[2]), "r"(a[3]),
                          "r"(b[nt][0]), "r"(b[nt][1]));
            }
        }
        __syncthreads();   // buffer-reuse guard
        buf = (buf + 1 == NSTAGE) ? 0 : buf + 1;
    }

    // ---- epilogue: bias + relu (+ tf32 rounding for h feeding the next layer) ----
#pragma unroll
    for (int mt = 0; mt < 4; mt++) {
        int r0 = row0 + m0w + mt * 16 + g;
#pragma unroll
        for (int nt = 0; nt < 4; nt++) {
            int cb = col0 + n0w + nt * 8 + tg * 2;
            if (cb < F) {
                float b0 = bias[cb], b1 = bias[cb + 1];
                float v0 = fmaxf(c[mt][nt][0] + b0, 0.f);
                float v1 = fmaxf(c[mt][nt][1] + b1, 0.f);
                float v2 = fmaxf(c[mt][nt][2] + b0, 0.f);
                float v3 = fmaxf(c[mt][nt][3] + b1, 0.f);
                if (do_round) {
                    v0 = rn_tf32f(v0); v1 = rn_tf32f(v1);
                    v2 = rn_tf32f(v2); v3 = rn_tf32f(v3);
                }
                if (r0 < M) *(float2*)(out + (size_t)r0 * F + cb) = make_float2(v0, v1);
                if (r0 + 8 < M) *(float2*)(out + (size_t)(r0 + 8) * F + cb) = make_float2(v2, v3);
            }
        }
    }
}

// ---------------- pooling ----------------
__global__ void k_zero_pool() {
    int i = blockIdx.x * blockDim.x + threadIdx.x;
    if (i < NG * F3) g_pool[i] = 0.f;
    if (i < NG) g_pcnt[i] = 0.f;
}
__global__ void k_pcnt(const int* __restrict__ batch) {
    int i = blockIdx.x * blockDim.x + threadIdx.x;
    if (i < NN) atomicAdd(&g_pcnt[batch[i]], 1.f);
}
__global__ void k_pool(const int* __restrict__ batch) {
    const int per = F3 / 4;
    long total = (long)NN * per;
    long i = (long)blockIdx.x * blockDim.x + threadIdx.x;
    if (i >= total) return;
    int n = (int)(i / per);
    int j = (int)(i % per);
    int b = batch[n];
    float4 v = ((const float4*)g_h1)[(long)n * per + j];
    float* base = g_pool + (long)b * F3 + j * 4;
    atomicAdd(base + 0, v.x);
    atomicAdd(base + 1, v.y);
    atomicAdd(base + 2, v.z);
    atomicAdd(base + 3, v.w);
}

// ---------------- final MLP ----------------
__global__ void k_mlp(const float* __restrict__ fw1, const float* __restrict__ fb1,
                      const float* __restrict__ fw2, const float* __restrict__ fb2,
                      float* __restrict__ out) {
    __shared__ float gbuf[F3];
    __shared__ float abuf[64];
    int g = blockIdx.x;
    int t = threadIdx.x;
    float invc = 1.f / fmaxf(g_pcnt[g], 1.f);
    for (int i = t; i < F3; i += blockDim.x)
        gbuf[i] = g_pool[(long)g * F3 + i] * invc;
    __syncthreads();
    if (t < 64) {
        float s = fb1[t];
        for (int k = 0; k < F3; k++) s += gbuf[k] * fw1[k * 64 + t];
        abuf[t] = fmaxf(s, 0.f);
    }
    __syncthreads();
    if (t == 0) {
        float o = fb2[0];
#pragma unroll
        for (int j = 0; j < 64; j++) o += abuf[j] * fw2[j];
        out[g] = o;
    }
}

// ---------------- launch ----------------
extern "C" void kernel_launch(void* const* d_in, const int* in_sizes, int n_in,
                              void* d_out, int out_size) {
    const float* x    = (const float*)d_in[0];
    const int*   ei   = (const int*)d_in[1];
    const int*   et   = (const int*)d_in[2];
    const int*   batch= (const int*)d_in[3];
    const float* W1   = (const float*)d_in[4];
    const float* r1   = (const float*)d_in[5];
    const float* b1   = (const float*)d_in[6];
    const float* W2   = (const float*)d_in[7];
    const float* r2   = (const float*)d_in[8];
    const float* b2   = (const float*)d_in[9];
    const float* W3   = (const float*)d_in[10];
    const float* r3   = (const float*)d_in[11];
    const float* b3   = (const float*)d_in[12];
    const float* fw1  = (const float*)d_in[13];
    const float* fb1  = (const float*)d_in[14];
    const float* fw2  = (const float*)d_in[15];
    const float* fb2  = (const float*)d_in[16];
    float* out = (float*)d_out;

    const int* srcI = ei;
    const int* dstI = ei + NE;

    cudaFuncSetAttribute(k_gemm_mma, cudaFuncAttributeMaxDynamicSharedMemorySize, SM_TOTAL_B);

    float *pB1, *pB2, *pB3, *pXr, *pH1, *pH2;
    cudaGetSymbolAddress((void**)&pB1, g_B1);
    cudaGetSymbolAddress((void**)&pB2, g_B2);
    cudaGetSymbolAddress((void**)&pB3, g_B3);
    cudaGetSymbolAddress((void**)&pXr, g_xr);
    cudaGetSymbolAddress((void**)&pH1, g_h1);
    cudaGetSymbolAddress((void**)&pH2, g_h2);

    // ---- weight / input pre-rounding (tf32) ----
    {
        long n1 = (long)320 * 1024;
        k_wconv<<<(int)((n1 / 4 + 255) / 256), 256>>>(W1, r1, pB1, (long)256 * 1024, n1);
        long n2 = (long)5120 * 1024;
        k_wconv<<<(int)((n2 / 4 + 255) / 256), 256>>>(W2, r2, pB2, (long)4096 * 1024, n2);
        long n3 = (long)5120 * 712;
        k_wconv<<<(int)((n3 / 4 + 255) / 256), 256>>>(W3, r3, pB3, (long)4096 * 712, n3);
        k_xconv<<<(NN * 64 / 4 + 255) / 256, 256>>>(x);
    }

    // ---- CSR build ----
    k_zero_cnt<<<(NBUCK + 255) / 256, 256>>>();
    k_count<<<(NE + 255) / 256, 256>>>(dstI, et);
    k_scanA<<<NSCANB, 256>>>();
    k_scanB<<<1, 32>>>();
    k_scanC<<<NSCANB, 256>>>();
    k_scatter<<<(NE + 255) / 256, 256>>>(srcI, dstI, et);

    // ---- layer 1: D=64 -> F=1024 ----
    {
        const int D = 64, F = 1024;
        int per = D / 4, npb = 256 / per;
        k_aggcsr<<<(NN + npb - 1) / npb, 256>>>(pXr, 0, D);
        dim3 grid((F + 127) / 128, (NN + 127) / 128);
        k_gemm_mma<<<grid, 256, SM_TOTAL_B>>>(pB1, b1, pXr, NN, D, F, 1, 1);
    }
    // ---- layer 2: D=1024 -> F=1024 ----
    {
        const int D = 1024, F = 1024;
        k_aggcsr<<<NN, 256>>>(nullptr, 1, D);
        dim3 grid((F + 127) / 128, (NN + 127) / 128);
        k_gemm_mma<<<grid, 256, SM_TOTAL_B>>>(pB2, b2, pH1, NN, D, F, 2, 1);
    }
    // ---- layer 3: D=1024 -> F=712 ----
    {
        const int D = 1024, F = F3;
        k_aggcsr<<<NN, 256>>>(nullptr, 2, D);
        dim3 grid((F + 127) / 128, (NN + 127) / 128);
        k_gemm_mma<<<grid, 256, SM_TOTAL_B>>>(pB3, b3, pH2, NN, D, F, 1, 0);
    }

    // ---- global mean pool + MLP ----
    k_zero_pool<<<(NG * F3 + 255) / 256, 256>>>();
    k_pcnt<<<(NN + 255) / 256, 256>>>(batch);
    {
        long tp = (long)NN * (F3 / 4);
        k_pool<<<(int)((tp + 255) / 256), 256>>>(batch);
    }
    k_mlp<<<NG, 128>>>(fw1, fb1, fw2, fb2, out);
}

// round 13
// speedup vs baseline: 1.0097x; 1.0097x over previous
#include <cuda_runtime.h>

#define NN      10000
#define NE      160000
#define NR      4
#define NG      256
#define F3      712
#define NBUCK   (NN * NR)
#define NSCANB  ((NBUCK + 255) / 256)

// ---------------- static device scratch (no allocations allowed) ----------------
__device__ float g_AX[(size_t)NN * 4 * 1024];   // aggregated operand [N, 4*D], tf32-rounded
__device__ float g_h1[(size_t)NN * 1024];       // layer1 out; reused for layer3 out
__device__ float g_h2[(size_t)NN * 1024];       // layer2 out
__device__ float g_xr[(size_t)NN * 64];         // tf32-rounded input x
__device__ float g_B1[320 * 1024];              // stacked [W1|root1], tf32-rounded
__device__ float g_B2[(size_t)5120 * 1024];     // stacked [W2|root2], tf32-rounded
__device__ float g_B3[(size_t)5120 * 712];      // stacked [W3|root3], tf32-rounded
__device__ int   g_cnt[NBUCK];
__device__ int   g_off[NBUCK];
__device__ int   g_cur[NBUCK];
__device__ int   g_bsum[NSCANB + 1];
__device__ int   g_es[NE];
__device__ float g_pool[NG * F3];
__device__ float g_pcnt[NG];

__device__ __forceinline__ unsigned rn_tf32(float x) {
    unsigned r;
    asm("cvt.rna.tf32.f32 %0, %1;" : "=r"(r) : "f"(x));
    return r;
}
__device__ __forceinline__ float rn_tf32f(float x) {
    return __uint_as_float(rn_tf32(x));
}

// ---------------- weight pre-conversion: dst = rn_tf32([W | root]) ----------------
__global__ void k_wconv(const float* __restrict__ W, const float* __restrict__ root,
                        float* __restrict__ dst, long nW, long nTot) {
    long i = ((long)blockIdx.x * blockDim.x + threadIdx.x) * 4;
    if (i >= nTot) return;
    float4 v = (i < nW) ? *(const float4*)(W + i) : *(const float4*)(root + (i - nW));
    v.x = rn_tf32f(v.x); v.y = rn_tf32f(v.y); v.z = rn_tf32f(v.z); v.w = rn_tf32f(v.w);
    *(float4*)(dst + i) = v;
}
__global__ void k_xconv(const float* __restrict__ x) {
    long i = ((long)blockIdx.x * blockDim.x + threadIdx.x) * 4;
    if (i >= (long)NN * 64) return;
    float4 v = *(const float4*)(x + i);
    v.x = rn_tf32f(v.x); v.y = rn_tf32f(v.y); v.z = rn_tf32f(v.z); v.w = rn_tf32f(v.w);
    *(float4*)(g_xr + i) = v;
}

// ---------------- CSR build ----------------
__global__ void k_zero_cnt() {
    int i = blockIdx.x * blockDim.x + threadIdx.x;
    if (i < NBUCK) g_cnt[i] = 0;
}
__global__ void k_count(const int* __restrict__ dst, const int* __restrict__ et) {
    int i = blockIdx.x * blockDim.x + threadIdx.x;
    if (i < NE) atomicAdd(&g_cnt[dst[i] * NR + et[i]], 1);
}
__global__ void k_scanA() {
    __shared__ int sd[256];
    int t = threadIdx.x;
    int i = blockIdx.x * 256 + t;
    int v = (i < NBUCK) ? g_cnt[i] : 0;
    sd[t] = v;
    __syncthreads();
#pragma unroll
    for (int o = 1; o < 256; o <<= 1) {
        int u = (t >= o) ? sd[t - o] : 0;
        __syncthreads();
        sd[t] += u;
        __syncthreads();
    }
    if (i < NBUCK) g_off[i] = sd[t] - v;
    if (t == 255) g_bsum[blockIdx.x] = sd[t];
}
__global__ void k_scanB() {
    if (threadIdx.x == 0) {
        int run = 0;
        for (int b = 0; b < NSCANB; b++) { int s = g_bsum[b]; g_bsum[b] = run; run += s; }
    }
}
__global__ void k_scanC() {
    int i = blockIdx.x * blockDim.x + threadIdx.x;
    if (i < NBUCK) {
        int o = g_off[i] + g_bsum[i >> 8];
        g_off[i] = o;
        g_cur[i] = o;
    }
}
__global__ void k_scatter(const int* __restrict__ src, const int* __restrict__ dst,
                          const int* __restrict__ et) {
    int e = blockIdx.x * blockDim.x + threadIdx.x;
    if (e < NE) {
        int b = dst[e] * NR + et[e];
        int pos = atomicAdd(&g_cur[b], 1);
        g_es[pos] = src[e];
    }
}

// ---------------- CSR aggregation (tf32-rounded output) ----------------
__global__ void k_aggcsr(const float* __restrict__ x0, int sel, int D) {
    int per = D >> 2;
    int npb = 256 / per;
    int local = threadIdx.x / per;
    int j = threadIdx.x - local * per;
    int n = blockIdx.x * npb + local;
    if (n >= NN) return;
    const float* x = (sel == 0) ? x0 : (sel == 1 ? g_h1 : g_h2);
    const float4* x4 = (const float4*)x;
    float4* out4 = (float4*)g_AX;
    size_t obase = (size_t)n * (NR * per);
#pragma unroll
    for (int r = 0; r < NR; r++) {
        int b = n * NR + r;
        int start = g_off[b];
        int cnt = g_cnt[b];
        float4 acc = make_float4(0.f, 0.f, 0.f, 0.f);
        for (int e = 0; e < cnt; e++) {
            int s = g_es[start + e];
            float4 v = x4[(size_t)s * per + j];
            acc.x += v.x; acc.y += v.y; acc.z += v.z; acc.w += v.w;
        }
        float inv = 1.f / fmaxf((float)cnt, 1.f);
        acc.x = rn_tf32f(acc.x * inv);
        acc.y = rn_tf32f(acc.y * inv);
        acc.z = rn_tf32f(acc.z * inv);
        acc.w = rn_tf32f(acc.w * inv);
        out4[obase + r * per + j] = acc;
    }
}

// ---------------- tf32 mma.sync stacked GEMM (pre-rounded) + bias + relu ----------
// CTA: 128M x 256N, BK=32, 8 warps of 64x64. 4-stage cp.async pipeline (dist 2),
// ONE barrier per chunk (buffer-reuse safety follows from the 2-iteration gap:
// buffer (ch+2)%4 was last read at iter ch-2, and the post-wait barrier of iter
// ch-1 guarantees all warps finished compute ch-2 before loads are issued).
// Logical A row n = [ g_AX[n, 0..4D) | H[n, 0..D) ], K = 5D, Kw = 4D. All pre-rounded.
// B = stacked pre-rounded [W|root], row-major [K, F].
#define AS_STRIDE 36
#define BS_STRIDE 264
#define ASZ (128 * AS_STRIDE)       // 4608 floats
#define BSZ (32 * BS_STRIDE)        // 8448 floats
#define NSTAGE 4
#define SM_TOTAL_B (NSTAGE * (ASZ + BSZ) * 4)   // 208896 bytes (1 CTA/SM)

__device__ __forceinline__ void cp_async16(unsigned dst, const float* src, int sz) {
    asm volatile("cp.async.ca.shared.global [%0], [%1], 16, %2;"
                 :: "r"(dst), "l"(src), "r"(sz));
}
__device__ __forceinline__ void cp_commit() {
    asm volatile("cp.async.commit_group;" ::: "memory");
}

__global__ __launch_bounds__(256)
void k_gemm_mma(const float* __restrict__ Bmat, const float* __restrict__ bias,
                const float* __restrict__ Hin,
                int M, int D, int F, int osel, int do_round) {
    extern __shared__ float sm[];
    const float* H = Hin;
    float* out = (osel == 1) ? g_h1 : g_h2;
    int K = 5 * D, Kw = 4 * D;

    int t = threadIdx.x, lane = t & 31, wid = t >> 5;
    int row0 = blockIdx.y * 128, col0 = blockIdx.x * 256;
    int m0w = (wid >> 2) * 64, n0w = (wid & 3) * 64;
    int g = lane >> 2, tg = lane & 3;
    int nch = K >> 5;

    float c[4][8][4];
#pragma unroll
    for (int i = 0; i < 4; i++)
#pragma unroll
        for (int j = 0; j < 8; j++)
#pragma unroll
            for (int k = 0; k < 4; k++) c[i][j][k] = 0.f;

    unsigned smb = (unsigned)__cvta_generic_to_shared(sm);

    auto load_chunk = [&](int ch, int buf) {
        unsigned as_b = smb + (unsigned)buf * ASZ * 4;
#pragma unroll
        for (int l = 0; l < 4; l++) {
            int id = t + (l << 8);
            int m = id >> 3, k4 = id & 7;
            int row = row0 + m;
            int krow = (ch << 5) + (k4 << 2);
            const float* src = (krow < Kw) ? (g_AX + (size_t)row * Kw + krow)
                                           : (H + (size_t)row * D + (krow - Kw));
            cp_async16(as_b + (unsigned)(m * AS_STRIDE + k4 * 4) * 4, src, (row < M) ? 16 : 0);
        }
        unsigned bs_b = smb + (unsigned)(NSTAGE * ASZ + buf * BSZ) * 4;
#pragma unroll
        for (int l = 0; l < 8; l++) {
            int id = t + (l << 8);
            int k = id >> 6, n4 = id & 63;
            int krow = (ch << 5) + k;
            int col = col0 + (n4 << 2);
            cp_async16(bs_b + (unsigned)(k * BS_STRIDE + n4 * 4) * 4,
                       Bmat + (size_t)krow * F + col, (col < F) ? 16 : 0);
        }
        cp_commit();
    };

    // prologue: fill 2 stages
    load_chunk(0, 0);
    if (nch > 1) load_chunk(1, 1);

    int buf = 0;
    for (int ch = 0; ch < nch; ch++) {
        // prefetch distance 2 (into a buffer idle for 2 iterations)
        if (ch + 2 < nch) load_chunk(ch + 2, (ch + 2) & (NSTAGE - 1));

        int rem = nch - 1 - ch;
        if (rem >= 2)      asm volatile("cp.async.wait_group 2;" ::: "memory");
        else if (rem == 1) asm volatile("cp.async.wait_group 1;" ::: "memory");
        else               asm volatile("cp.async.wait_group 0;" ::: "memory");
        __syncthreads();   // single barrier per chunk

        const float* As = sm + buf * ASZ;
        const float* Bs = sm + NSTAGE * ASZ + buf * BSZ;

#pragma unroll
        for (int kk = 0; kk < 32; kk += 8) {
            unsigned b[8][2];
#pragma unroll
            for (int nt = 0; nt < 8; nt++) {
                int n = n0w + nt * 8 + g;
                b[nt][0] = __float_as_uint(Bs[(kk + tg) * BS_STRIDE + n]);
                b[nt][1] = __float_as_uint(Bs[(kk + 4 + tg) * BS_STRIDE + n]);
            }
#pragma unroll
            for (int mt = 0; mt < 4; mt++) {
                int m = m0w + mt * 16 + g;
                unsigned a[4];
                a[0] = __float_as_uint(As[m * AS_STRIDE + kk + tg]);
                a[1] = __float_as_uint(As[(m + 8) * AS_STRIDE + kk + tg]);
                a[2] = __float_as_uint(As[m * AS_STRIDE + kk + 4 + tg]);
                a[3] = __float_as_uint(As[(m + 8) * AS_STRIDE + kk + 4 + tg]);
#pragma unroll
                for (int nt = 0; nt < 8; nt++)
                    asm volatile(
                        "mma.sync.aligned.m16n8k8.row.col.f32.tf32.tf32.f32 "
                        "{%0,%1,%2,%3},{%4,%5,%6,%7},{%8,%9},{%0,%1,%2,%3};"
                        : "+f"(c[mt][nt][0]), "+f"(c[mt][nt][1]),
                          "+f"(c[mt][nt][2]), "+f"(c[mt][nt][3])
                        : "r"(a[0]), "r"(a[1]), "r"(a[2]), "r"(a[3]),
                          "r"(b[nt][0]), "r"(b[nt][1]));
            }
        }
        buf = (buf + 1) & (NSTAGE - 1);
    }

    // ---- epilogue: bias + relu (+ tf32 rounding for h feeding the next layer) ----
#pragma unroll
    for (int mt = 0; mt < 4; mt++) {
        int r0 = row0 + m0w + mt * 16 + g;
#pragma unroll
        for (int nt = 0; nt < 8; nt++) {
            int cb = col0 + n0w + nt * 8 + tg * 2;
            if (cb < F) {
                float b0 = bias[cb], b1 = bias[cb + 1];
                float v0 = fmaxf(c[mt][nt][0] + b0, 0.f);
                float v1 = fmaxf(c[mt][nt][1] + b1, 0.f);
                float v2 = fmaxf(c[mt][nt][2] + b0, 0.f);
                float v3 = fmaxf(c[mt][nt][3] + b1, 0.f);
                if (do_round) {
                    v0 = rn_tf32f(v0); v1 = rn_tf32f(v1);
                    v2 = rn_tf32f(v2); v3 = rn_tf32f(v3);
                }
                if (r0 < M) *(float2*)(out + (size_t)r0 * F + cb) = make_float2(v0, v1);
                if (r0 + 8 < M) *(float2*)(out + (size_t)(r0 + 8) * F + cb) = make_float2(v2, v3);
            }
        }
    }
}

// ---------------- pooling ----------------
__global__ void k_zero_pool() {
    int i = blockIdx.x * blockDim.x + threadIdx.x;
    if (i < NG * F3) g_pool[i] = 0.f;
    if (i < NG) g_pcnt[i] = 0.f;
}
__global__ void k_pcnt(const int* __restrict__ batch) {
    int i = blockIdx.x * blockDim.x + threadIdx.x;
    if (i < NN) atomicAdd(&g_pcnt[batch[i]], 1.f);
}
__global__ void k_pool(const int* __restrict__ batch) {
    const int per = F3 / 4;
    long total = (long)NN * per;
    long i = (long)blockIdx.x * blockDim.x + threadIdx.x;
    if (i >= total) return;
    int n = (int)(i / per);
    int j = (int)(i % per);
    int b = batch[n];
    float4 v = ((const float4*)g_h1)[(long)n * per + j];
    float* base = g_pool + (long)b * F3 + j * 4;
    atomicAdd(base + 0, v.x);
    atomicAdd(base + 1, v.y);
    atomicAdd(base + 2, v.z);
    atomicAdd(base + 3, v.w);
}

// ---------------- final MLP ----------------
__global__ void k_mlp(const float* __restrict__ fw1, const float* __restrict__ fb1,
                      const float* __restrict__ fw2, const float* __restrict__ fb2,
                      float* __restrict__ out) {
    __shared__ float gbuf[F3];
    __shared__ float abuf[64];
    int g = blockIdx.x;
    int t = threadIdx.x;
    float invc = 1.f / fmaxf(g_pcnt[g], 1.f);
    for (int i = t; i < F3; i += blockDim.x)
        gbuf[i] = g_pool[(long)g * F3 + i] * invc;
    __syncthreads();
    if (t < 64) {
        float s = fb1[t];
        for (int k = 0; k < F3; k++) s += gbuf[k] * fw1[k * 64 + t];
        abuf[t] = fmaxf(s, 0.f);
    }
    __syncthreads();
    if (t == 0) {
        float o = fb2[0];
#pragma unroll
        for (int j = 0; j < 64; j++) o += abuf[j] * fw2[j];
        out[g] = o;
    }
}

// ---------------- launch ----------------
extern "C" void kernel_launch(void* const* d_in, const int* in_sizes, int n_in,
                              void* d_out, int out_size) {
    const float* x    = (const float*)d_in[0];
    const int*   ei   = (const int*)d_in[1];
    const int*   et   = (const int*)d_in[2];
    const int*   batch= (const int*)d_in[3];
    const float* W1   = (const float*)d_in[4];
    const float* r1   = (const float*)d_in[5];
    const float* b1   = (const float*)d_in[6];
    const float* W2   = (const float*)d_in[7];
    const float* r2   = (const float*)d_in[8];
    const float* b2   = (const float*)d_in[9];
    const float* W3   = (const float*)d_in[10];
    const float* r3   = (const float*)d_in[11];
    const float* b3   = (const float*)d_in[12];
    const float* fw1  = (const float*)d_in[13];
    const float* fb1  = (const float*)d_in[14];
    const float* fw2  = (const float*)d_in[15];
    const float* fb2  = (const float*)d_in[16];
    float* out = (float*)d_out;

    const int* srcI = ei;
    const int* dstI = ei + NE;

    cudaFuncSetAttribute(k_gemm_mma, cudaFuncAttributeMaxDynamicSharedMemorySize, SM_TOTAL_B);

    float *pB1, *pB2, *pB3, *pXr, *pH1, *pH2;
    cudaGetSymbolAddress((void**)&pB1, g_B1);
    cudaGetSymbolAddress((void**)&pB2, g_B2);
    cudaGetSymbolAddress((void**)&pB3, g_B3);
    cudaGetSymbolAddress((void**)&pXr, g_xr);
    cudaGetSymbolAddress((void**)&pH1, g_h1);
    cudaGetSymbolAddress((void**)&pH2, g_h2);

    // ---- weight / input pre-rounding (tf32) ----
    {
        long n1 = (long)320 * 1024;
        k_wconv<<<(int)((n1 / 4 + 255) / 256), 256>>>(W1, r1, pB1, (long)256 * 1024, n1);
        long n2 = (long)5120 * 1024;
        k_wconv<<<(int)((n2 / 4 + 255) / 256), 256>>>(W2, r2, pB2, (long)4096 * 1024, n2);
        long n3 = (long)5120 * 712;
        k_wconv<<<(int)((n3 / 4 + 255) / 256), 256>>>(W3, r3, pB3, (long)4096 * 712, n3);
        k_xconv<<<(NN * 64 / 4 + 255) / 256, 256>>>(x);
    }

    // ---- CSR build ----
    k_zero_cnt<<<(NBUCK + 255) / 256, 256>>>();
    k_count<<<(NE + 255) / 256, 256>>>(dstI, et);
    k_scanA<<<NSCANB, 256>>>();
    k_scanB<<<1, 32>>>();
    k_scanC<<<NSCANB, 256>>>();
    k_scatter<<<(NE + 255) / 256, 256>>>(srcI, dstI, et);

    // ---- layer 1: D=64 -> F=1024 ----
    {
        const int D = 64, F = 1024;
        int per = D / 4, npb = 256 / per;
        k_aggcsr<<<(NN + npb - 1) / npb, 256>>>(pXr, 0, D);
        dim3 grid((F + 255) / 256, (NN + 127) / 128);
        k_gemm_mma<<<grid, 256, SM_TOTAL_B>>>(pB1, b1, pXr, NN, D, F, 1, 1);
    }
    // ---- layer 2: D=1024 -> F=1024 ----
    {
        const int D = 1024, F = 1024;
        k_aggcsr<<<NN, 256>>>(nullptr, 1, D);
        dim3 grid((F + 255) / 256, (NN + 127) / 128);
        k_gemm_mma<<<grid, 256, SM_TOTAL_B>>>(pB2, b2, pH1, NN, D, F, 2, 1);
    }
    // ---- layer 3: D=1024 -> F=712 ----
    {
        const int D = 1024, F = F3;
        k_aggcsr<<<NN, 256>>>(nullptr, 2, D);
        dim3 grid((F + 255) / 256, (NN + 127) / 128);
        k_gemm_mma<<<grid, 256, SM_TOTAL_B>>>(pB3, b3, pH2, NN, D, F, 1, 0);
    }

    // ---- global mean pool + MLP ----
    k_zero_pool<<<(NG * F3 + 255) / 256, 256>>>();
    k_pcnt<<<(NN + 255) / 256, 256>>>(batch);
    {
        long tp = (long)NN * (F3 / 4);
        k_pool<<<(int)((tp + 255) / 256), 256>>>(batch);
    }
    k_mlp<<<NG, 128>>>(fw1, fb1, fw2, fb2, out);
}

// round 14
// speedup vs baseline: 1.1792x; 1.1679x over previous
#include <cuda_runtime.h>

#define NN      10000
#define NE      160000
#define NR      4
#define NG      256
#define F3      712
#define NBUCK   (NN * NR)
#define NSCANB  ((NBUCK + 255) / 256)

// ---------------- static device scratch (no allocations allowed) ----------------
__device__ float g_AX[(size_t)NN * 4 * 1024];   // aggregated operand [N, 4*D], tf32-rounded
__device__ float g_h1[(size_t)NN * 1024];       // layer1 out; reused for layer3 out
__device__ float g_h2[(size_t)NN * 1024];       // layer2 out
__device__ float g_xr[(size_t)NN * 64];         // tf32-rounded input x
__device__ float g_B1[320 * 1024];              // stacked [W1|root1], tf32-rounded
__device__ float g_B2[(size_t)5120 * 1024];     // stacked [W2|root2], tf32-rounded
__device__ float g_B3[(size_t)5120 * 712];      // stacked [W3|root3], tf32-rounded
__device__ int   g_cnt[NBUCK];
__device__ int   g_off[NBUCK];
__device__ int   g_cur[NBUCK];
__device__ int   g_bsum[NSCANB + 1];
__device__ int   g_es[NE];

__device__ __forceinline__ unsigned rn_tf32(float x) {
    unsigned r;
    asm("cvt.rna.tf32.f32 %0, %1;" : "=r"(r) : "f"(x));
    return r;
}
__device__ __forceinline__ float rn_tf32f(float x) {
    return __uint_as_float(rn_tf32(x));
}

// ---------------- weight pre-conversion: dst = rn_tf32([W | root]) ----------------
__global__ void k_wconv(const float* __restrict__ W, const float* __restrict__ root,
                        float* __restrict__ dst, long nW, long nTot) {
    long i = ((long)blockIdx.x * blockDim.x + threadIdx.x) * 4;
    if (i >= nTot) return;
    float4 v = (i < nW) ? *(const float4*)(W + i) : *(const float4*)(root + (i - nW));
    v.x = rn_tf32f(v.x); v.y = rn_tf32f(v.y); v.z = rn_tf32f(v.z); v.w = rn_tf32f(v.w);
    *(float4*)(dst + i) = v;
}
__global__ void k_xconv(const float* __restrict__ x) {
    long i = ((long)blockIdx.x * blockDim.x + threadIdx.x) * 4;
    if (i >= (long)NN * 64) return;
    float4 v = *(const float4*)(x + i);
    v.x = rn_tf32f(v.x); v.y = rn_tf32f(v.y); v.z = rn_tf32f(v.z); v.w = rn_tf32f(v.w);
    *(float4*)(g_xr + i) = v;
}

// ---------------- CSR build ----------------
__global__ void k_zero_cnt() {
    int i = blockIdx.x * blockDim.x + threadIdx.x;
    if (i < NBUCK) g_cnt[i] = 0;
}
__global__ void k_count(const int* __restrict__ dst, const int* __restrict__ et) {
    int i = blockIdx.x * blockDim.x + threadIdx.x;
    if (i < NE) atomicAdd(&g_cnt[dst[i] * NR + et[i]], 1);
}
__global__ void k_scanA() {
    __shared__ int sd[256];
    int t = threadIdx.x;
    int i = blockIdx.x * 256 + t;
    int v = (i < NBUCK) ? g_cnt[i] : 0;
    sd[t] = v;
    __syncthreads();
#pragma unroll
    for (int o = 1; o < 256; o <<= 1) {
        int u = (t >= o) ? sd[t - o] : 0;
        __syncthreads();
        sd[t] += u;
        __syncthreads();
    }
    if (i < NBUCK) g_off[i] = sd[t] - v;
    if (t == 255) g_bsum[blockIdx.x] = sd[t];
}
// parallel exclusive scan of the NSCANB block sums (single block)
__global__ void k_scanB() {
    __shared__ int sd[256];
    int t = threadIdx.x;
    int v = (t < NSCANB) ? g_bsum[t] : 0;
    sd[t] = v;
    __syncthreads();
#pragma unroll
    for (int o = 1; o < 256; o <<= 1) {
        int u = (t >= o) ? sd[t - o] : 0;
        __syncthreads();
        sd[t] += u;
        __syncthreads();
    }
    if (t < NSCANB) g_bsum[t] = sd[t] - v;
}
__global__ void k_scanC() {
    int i = blockIdx.x * blockDim.x + threadIdx.x;
    if (i < NBUCK) {
        int o = g_off[i] + g_bsum[i >> 8];
        g_off[i] = o;
        g_cur[i] = o;
    }
}
__global__ void k_scatter(const int* __restrict__ src, const int* __restrict__ dst,
                          const int* __restrict__ et) {
    int e = blockIdx.x * blockDim.x + threadIdx.x;
    if (e < NE) {
        int b = dst[e] * NR + et[e];
        int pos = atomicAdd(&g_cur[b], 1);
        g_es[pos] = src[e];
    }
}

// ---------------- CSR aggregation (tf32-rounded output) ----------------
__global__ void k_aggcsr(const float* __restrict__ x0, int sel, int D) {
    int per = D >> 2;
    int npb = 256 / per;
    int local = threadIdx.x / per;
    int j = threadIdx.x - local * per;
    int n = blockIdx.x * npb + local;
    if (n >= NN) return;
    const float* x = (sel == 0) ? x0 : (sel == 1 ? g_h1 : g_h2);
    const float4* x4 = (const float4*)x;
    float4* out4 = (float4*)g_AX;
    size_t obase = (size_t)n * (NR * per);
#pragma unroll
    for (int r = 0; r < NR; r++) {
        int b = n * NR + r;
        int start = g_off[b];
        int cnt = g_cnt[b];
        float4 acc = make_float4(0.f, 0.f, 0.f, 0.f);
        for (int e = 0; e < cnt; e++) {
            int s = g_es[start + e];
            float4 v = x4[(size_t)s * per + j];
            acc.x += v.x; acc.y += v.y; acc.z += v.z; acc.w += v.w;
        }
        float inv = 1.f / fmaxf((float)cnt, 1.f);
        acc.x = rn_tf32f(acc.x * inv);
        acc.y = rn_tf32f(acc.y * inv);
        acc.z = rn_tf32f(acc.z * inv);
        acc.w = rn_tf32f(acc.w * inv);
        out4[obase + r * per + j] = acc;
    }
}

// ---------------- tf32 mma.sync stacked GEMM (pre-rounded) + bias + relu ----------
// CTA: 128M x 256N, BK=32, 8 warps of 64x64. 3-stage cp.async pipeline (dist 2).
// Logical A row n = [ g_AX[n, 0..4D) | H[n, 0..D) ], K = 5D, Kw = 4D. All pre-rounded.
// B = stacked pre-rounded [W|root], row-major [K, F].
#define AS_STRIDE 36
#define BS_STRIDE 264
#define ASZ (128 * AS_STRIDE)       // 4608 floats
#define BSZ (32 * BS_STRIDE)        // 8448 floats
#define NSTAGE 3
#define SM_TOTAL_B (NSTAGE * (ASZ + BSZ) * 4)   // 156672 bytes

__device__ __forceinline__ void cp_async16(unsigned dst, const float* src, int sz) {
    asm volatile("cp.async.ca.shared.global [%0], [%1], 16, %2;"
                 :: "r"(dst), "l"(src), "r"(sz));
}
__device__ __forceinline__ void cp_commit() {
    asm volatile("cp.async.commit_group;" ::: "memory");
}

__global__ __launch_bounds__(256)
void k_gemm_mma(const float* __restrict__ Bmat, const float* __restrict__ bias,
                const float* __restrict__ Hin,
                int M, int D, int F, int osel, int do_round) {
    extern __shared__ float sm[];
    const float* H = Hin;
    float* out = (osel == 1) ? g_h1 : g_h2;
    int K = 5 * D, Kw = 4 * D;

    int t = threadIdx.x, lane = t & 31, wid = t >> 5;
    int row0 = blockIdx.y * 128, col0 = blockIdx.x * 256;
    int m0w = (wid >> 2) * 64, n0w = (wid & 3) * 64;
    int g = lane >> 2, tg = lane & 3;
    int nch = K >> 5;

    float c[4][8][4];
#pragma unroll
    for (int i = 0; i < 4; i++)
#pragma unroll
        for (int j = 0; j < 8; j++)
#pragma unroll
            for (int k = 0; k < 4; k++) c[i][j][k] = 0.f;

    unsigned smb = (unsigned)__cvta_generic_to_shared(sm);

    auto load_chunk = [&](int ch, int buf) {
        unsigned as_b = smb + (unsigned)buf * ASZ * 4;
#pragma unroll
        for (int l = 0; l < 4; l++) {
            int id = t + (l << 8);
            int m = id >> 3, k4 = id & 7;
            int row = row0 + m;
            int krow = (ch << 5) + (k4 << 2);
            const float* src = (krow < Kw) ? (g_AX + (size_t)row * Kw + krow)
                                           : (H + (size_t)row * D + (krow - Kw));
            cp_async16(as_b + (unsigned)(m * AS_STRIDE + k4 * 4) * 4, src, (row < M) ? 16 : 0);
        }
        unsigned bs_b = smb + (unsigned)(NSTAGE * ASZ + buf * BSZ) * 4;
#pragma unroll
        for (int l = 0; l < 8; l++) {
            int id = t + (l << 8);
            int k = id >> 6, n4 = id & 63;
            int krow = (ch << 5) + k;
            int col = col0 + (n4 << 2);
            cp_async16(bs_b + (unsigned)(k * BS_STRIDE + n4 * 4) * 4,
                       Bmat + (size_t)krow * F + col, (col < F) ? 16 : 0);
        }
        cp_commit();
    };

    // prologue: fill 2 stages
    load_chunk(0, 0);
    if (nch > 1) load_chunk(1, 1);

    int buf = 0;
    for (int ch = 0; ch < nch; ch++) {
        if (ch + 2 < nch) load_chunk(ch + 2, (ch + 2) % NSTAGE);

        int rem = nch - 1 - ch;
        if (rem >= 2)      asm volatile("cp.async.wait_group 2;" ::: "memory");
        else if (rem == 1) asm volatile("cp.async.wait_group 1;" ::: "memory");
        else               asm volatile("cp.async.wait_group 0;" ::: "memory");
        __syncthreads();

        const float* As = sm + buf * ASZ;
        const float* Bs = sm + NSTAGE * ASZ + buf * BSZ;

#pragma unroll
        for (int kk = 0; kk < 32; kk += 8) {
            unsigned b[8][2];
#pragma unroll
            for (int nt = 0; nt < 8; nt++) {
                int n = n0w + nt * 8 + g;
                b[nt][0] = __float_as_uint(Bs[(kk + tg) * BS_STRIDE + n]);
                b[nt][1] = __float_as_uint(Bs[(kk + 4 + tg) * BS_STRIDE + n]);
            }
#pragma unroll
            for (int mt = 0; mt < 4; mt++) {
                int m = m0w + mt * 16 + g;
                unsigned a[4];
                a[0] = __float_as_uint(As[m * AS_STRIDE + kk + tg]);
                a[1] = __float_as_uint(As[(m + 8) * AS_STRIDE + kk + tg]);
                a[2] = __float_as_uint(As[m * AS_STRIDE + kk + 4 + tg]);
                a[3] = __float_as_uint(As[(m + 8) * AS_STRIDE + kk + 4 + tg]);
#pragma unroll
                for (int nt = 0; nt < 8; nt++)
                    asm volatile(
                        "mma.sync.aligned.m16n8k8.row.col.f32.tf32.tf32.f32 "
                        "{%0,%1,%2,%3},{%4,%5,%6,%7},{%8,%9},{%0,%1,%2,%3};"
                        : "+f"(c[mt][nt][0]), "+f"(c[mt][nt][1]),
                          "+f"(c[mt][nt][2]), "+f"(c[mt][nt][3])
                        : "r"(a[0]), "r"(a[1]), "r"(a[2]), "r"(a[3]),
                          "r"(b[nt][0]), "r"(b[nt][1]));
            }
        }
        __syncthreads();   // buffer-reuse guard
        buf = (buf + 1 == NSTAGE) ? 0 : buf + 1;
    }

    // ---- epilogue: bias + relu (+ tf32 rounding for h feeding the next layer) ----
#pragma unroll
    for (int mt = 0; mt < 4; mt++) {
        int r0 = row0 + m0w + mt * 16 + g;
#pragma unroll
        for (int nt = 0; nt < 8; nt++) {
            int cb = col0 + n0w + nt * 8 + tg * 2;
            if (cb < F) {
                float b0 = bias[cb], b1 = bias[cb + 1];
                float v0 = fmaxf(c[mt][nt][0] + b0, 0.f);
                float v1 = fmaxf(c[mt][nt][1] + b1, 0.f);
                float v2 = fmaxf(c[mt][nt][2] + b0, 0.f);
                float v3 = fmaxf(c[mt][nt][3] + b1, 0.f);
                if (do_round) {
                    v0 = rn_tf32f(v0); v1 = rn_tf32f(v1);
                    v2 = rn_tf32f(v2); v3 = rn_tf32f(v3);
                }
                if (r0 < M) *(float2*)(out + (size_t)r0 * F + cb) = make_float2(v0, v1);
                if (r0 + 8 < M) *(float2*)(out + (size_t)(r0 + 8) * F + cb) = make_float2(v2, v3);
            }
        }
    }
}

// ---------------- fused pool + MLP (batch is sorted -> contiguous node ranges) ----
__global__ void k_poolmlp(const int* __restrict__ batch,
                          const float* __restrict__ fw1, const float* __restrict__ fb1,
                          const float* __restrict__ fw2, const float* __restrict__ fb2,
                          float* __restrict__ out) {
    __shared__ float gbuf[F3];
    __shared__ float abuf[64];
    __shared__ int range[2];
    int g = blockIdx.x;
    int t = threadIdx.x;
    if (t < 2) {
        int key = g + t;             // t=0: lower_bound(g); t=1: lower_bound(g+1)
        int lo = 0, hi = NN;
        while (lo < hi) {
            int mid = (lo + hi) >> 1;
            if (batch[mid] < key) lo = mid + 1; else hi = mid;
        }
        range[t] = lo;
    }
    __syncthreads();
    int s = range[0], e = range[1];
    float invc = 1.f / fmaxf((float)(e - s), 1.f);
    for (int i = t; i < F3; i += 256) {
        float acc = 0.f;
        for (int n = s; n < e; n++) acc += g_h1[(size_t)n * F3 + i];
        gbuf[i] = acc * invc;
    }
    __syncthreads();
    if (t < 64) {
        float ssum = fb1[t];
        for (int k = 0; k < F3; k++) ssum += gbuf[k] * fw1[k * 64 + t];
        abuf[t] = fmaxf(ssum, 0.f);
    }
    __syncthreads();
    if (t == 0) {
        float o = fb2[0];
#pragma unroll
        for (int j = 0; j < 64; j++) o += abuf[j] * fw2[j];
        out[g] = o;
    }
}

// ---------------- launch ----------------
extern "C" void kernel_launch(void* const* d_in, const int* in_sizes, int n_in,
                              void* d_out, int out_size) {
    const float* x    = (const float*)d_in[0];
    const int*   ei   = (const int*)d_in[1];
    const int*   et   = (const int*)d_in[2];
    const int*   batch= (const int*)d_in[3];
    const float* W1   = (const float*)d_in[4];
    const float* r1   = (const float*)d_in[5];
    const float* b1   = (const float*)d_in[6];
    const float* W2   = (const float*)d_in[7];
    const float* r2   = (const float*)d_in[8];
    const float* b2   = (const float*)d_in[9];
    const float* W3   = (const float*)d_in[10];
    const float* r3   = (const float*)d_in[11];
    const float* b3   = (const float*)d_in[12];
    const float* fw1  = (const float*)d_in[13];
    const float* fb1  = (const float*)d_in[14];
    const float* fw2  = (const float*)d_in[15];
    const float* fb2  = (const float*)d_in[16];
    float* out = (float*)d_out;

    const int* srcI = ei;
    const int* dstI = ei + NE;

    cudaFuncSetAttribute(k_gemm_mma, cudaFuncAttributeMaxDynamicSharedMemorySize, SM_TOTAL_B);

    float *pB1, *pB2, *pB3, *pXr, *pH1, *pH2;
    cudaGetSymbolAddress((void**)&pB1, g_B1);
    cudaGetSymbolAddress((void**)&pB2, g_B2);
    cudaGetSymbolAddress((void**)&pB3, g_B3);
    cudaGetSymbolAddress((void**)&pXr, g_xr);
    cudaGetSymbolAddress((void**)&pH1, g_h1);
    cudaGetSymbolAddress((void**)&pH2, g_h2);

    // ---- weight / input pre-rounding (tf32) ----
    {
        long n1 = (long)320 * 1024;
        k_wconv<<<(int)((n1 / 4 + 255) / 256), 256>>>(W1, r1, pB1, (long)256 * 1024, n1);
        long n2 = (long)5120 * 1024;
        k_wconv<<<(int)((n2 / 4 + 255) / 256), 256>>>(W2, r2, pB2, (long)4096 * 1024, n2);
        long n3 = (long)5120 * 712;
        k_wconv<<<(int)((n3 / 4 + 255) / 256), 256>>>(W3, r3, pB3, (long)4096 * 712, n3);
        k_xconv<<<(NN * 64 / 4 + 255) / 256, 256>>>(x);
    }

    // ---- CSR build ----
    k_zero_cnt<<<(NBUCK + 255) / 256, 256>>>();
    k_count<<<(NE + 255) / 256, 256>>>(dstI, et);
    k_scanA<<<NSCANB, 256>>>();
    k_scanB<<<1, 256>>>();
    k_scanC<<<NSCANB, 256>>>();
    k_scatter<<<(NE + 255) / 256, 256>>>(srcI, dstI, et);

    // ---- layer 1: D=64 -> F=1024 ----
    {
        const int D = 64, F = 1024;
        int per = D / 4, npb = 256 / per;
        k_aggcsr<<<(NN + npb - 1) / npb, 256>>>(pXr, 0, D);
        dim3 grid((F + 255) / 256, (NN + 127) / 128);
        k_gemm_mma<<<grid, 256, SM_TOTAL_B>>>(pB1, b1, pXr, NN, D, F, 1, 1);
    }
    // ---- layer 2: D=1024 -> F=1024 ----
    {
        const int D = 1024, F = 1024;
        k_aggcsr<<<NN, 256>>>(nullptr, 1, D);
        dim3 grid((F + 255) / 256, (NN + 127) / 128);
        k_gemm_mma<<<grid, 256, SM_TOTAL_B>>>(pB2, b2, pH1, NN, D, F, 2, 1);
    }
    // ---- layer 3: D=1024 -> F=712 ----
    {
        const int D = 1024, F = F3;
        k_aggcsr<<<NN, 256>>>(nullptr, 2, D);
        dim3 grid((F + 255) / 256, (NN + 127) / 128);
        k_gemm_mma<<<grid, 256, SM_TOTAL_B>>>(pB3, b3, pH2, NN, D, F, 1, 0);
    }

    // ---- fused global mean pool + MLP ----
    k_poolmlp<<<NG, 256>>>(batch, fw1, fb1, fw2, fb2, out);
}

// round 15
// speedup vs baseline: 1.3407x; 1.1369x over previous
#include <cuda_runtime.h>

#define NN      10000
#define NE      160000
#define NR      4
#define NG      256
#define F3      712
#define NBUCK   (NN * NR)
#define NSCANB  ((NBUCK + 255) / 256)

// ---------------- static device scratch (no allocations allowed) ----------------
__device__ float g_AX[(size_t)NN * 4 * 1024];   // aggregated operand [N, 4*D], tf32-rounded
__device__ float g_h1[(size_t)NN * 1024];       // layer1 out; reused for layer3 out
__device__ float g_h2[(size_t)NN * 1024];       // layer2 out
__device__ float g_xr[(size_t)NN * 64];         // tf32-rounded input x
__device__ float g_B1[320 * 1024];              // stacked [W1|root1], tf32-rounded
__device__ float g_B2[(size_t)5120 * 1024];     // stacked [W2|root2], tf32-rounded
__device__ float g_B3[(size_t)5120 * 712];      // stacked [W3|root3], tf32-rounded
__device__ float g_part[(size_t)3 * NN * 1024]; // split-K partial sums
__device__ int   g_cnt[NBUCK];
__device__ int   g_off[NBUCK];
__device__ int   g_cur[NBUCK];
__device__ int   g_bsum[NSCANB + 1];
__device__ int   g_es[NE];

__device__ __forceinline__ unsigned rn_tf32(float x) {
    unsigned r;
    asm("cvt.rna.tf32.f32 %0, %1;" : "=r"(r) : "f"(x));
    return r;
}
__device__ __forceinline__ float rn_tf32f(float x) {
    return __uint_as_float(rn_tf32(x));
}

// ---------------- weight pre-conversion: dst = rn_tf32([W | root]) ----------------
__global__ void k_wconv(const float* __restrict__ W, const float* __restrict__ root,
                        float* __restrict__ dst, long nW, long nTot) {
    long i = ((long)blockIdx.x * blockDim.x + threadIdx.x) * 4;
    if (i >= nTot) return;
    float4 v = (i < nW) ? *(const float4*)(W + i) : *(const float4*)(root + (i - nW));
    v.x = rn_tf32f(v.x); v.y = rn_tf32f(v.y); v.z = rn_tf32f(v.z); v.w = rn_tf32f(v.w);
    *(float4*)(dst + i) = v;
}
__global__ void k_xconv(const float* __restrict__ x) {
    long i = ((long)blockIdx.x * blockDim.x + threadIdx.x) * 4;
    if (i >= (long)NN * 64) return;
    float4 v = *(const float4*)(x + i);
    v.x = rn_tf32f(v.x); v.y = rn_tf32f(v.y); v.z = rn_tf32f(v.z); v.w = rn_tf32f(v.w);
    *(float4*)(g_xr + i) = v;
}

// ---------------- CSR build ----------------
__global__ void k_zero_cnt() {
    int i = blockIdx.x * blockDim.x + threadIdx.x;
    if (i < NBUCK) g_cnt[i] = 0;
}
__global__ void k_count(const int* __restrict__ dst, const int* __restrict__ et) {
    int i = blockIdx.x * blockDim.x + threadIdx.x;
    if (i < NE) atomicAdd(&g_cnt[dst[i] * NR + et[i]], 1);
}
__global__ void k_scanA() {
    __shared__ int sd[256];
    int t = threadIdx.x;
    int i = blockIdx.x * 256 + t;
    int v = (i < NBUCK) ? g_cnt[i] : 0;
    sd[t] = v;
    __syncthreads();
#pragma unroll
    for (int o = 1; o < 256; o <<= 1) {
        int u = (t >= o) ? sd[t - o] : 0;
        __syncthreads();
        sd[t] += u;
        __syncthreads();
    }
    if (i < NBUCK) g_off[i] = sd[t] - v;
    if (t == 255) g_bsum[blockIdx.x] = sd[t];
}
__global__ void k_scanB() {
    __shared__ int sd[256];
    int t = threadIdx.x;
    int v = (t < NSCANB) ? g_bsum[t] : 0;
    sd[t] = v;
    __syncthreads();
#pragma unroll
    for (int o = 1; o < 256; o <<= 1) {
        int u = (t >= o) ? sd[t - o] : 0;
        __syncthreads();
        sd[t] += u;
        __syncthreads();
    }
    if (t < NSCANB) g_bsum[t] = sd[t] - v;
}
__global__ void k_scanC() {
    int i = blockIdx.x * blockDim.x + threadIdx.x;
    if (i < NBUCK) {
        int o = g_off[i] + g_bsum[i >> 8];
        g_off[i] = o;
        g_cur[i] = o;
    }
}
__global__ void k_scatter(const int* __restrict__ src, const int* __restrict__ dst,
                          const int* __restrict__ et) {
    int e = blockIdx.x * blockDim.x + threadIdx.x;
    if (e < NE) {
        int b = dst[e] * NR + et[e];
        int pos = atomicAdd(&g_cur[b], 1);
        g_es[pos] = src[e];
    }
}

// ---------------- CSR aggregation (tf32-rounded output) ----------------
__global__ void k_aggcsr(const float* __restrict__ x0, int sel, int D) {
    int per = D >> 2;
    int npb = 256 / per;
    int local = threadIdx.x / per;
    int j = threadIdx.x - local * per;
    int n = blockIdx.x * npb + local;
    if (n >= NN) return;
    const float* x = (sel == 0) ? x0 : (sel == 1 ? g_h1 : g_h2);
    const float4* x4 = (const float4*)x;
    float4* out4 = (float4*)g_AX;
    size_t obase = (size_t)n * (NR * per);
#pragma unroll
    for (int r = 0; r < NR; r++) {
        int b = n * NR + r;
        int start = g_off[b];
        int cnt = g_cnt[b];
        float4 acc = make_float4(0.f, 0.f, 0.f, 0.f);
        for (int e = 0; e < cnt; e++) {
            int s = g_es[start + e];
            float4 v = x4[(size_t)s * per + j];
            acc.x += v.x; acc.y += v.y; acc.z += v.z; acc.w += v.w;
        }
        float inv = 1.f / fmaxf((float)cnt, 1.f);
        acc.x = rn_tf32f(acc.x * inv);
        acc.y = rn_tf32f(acc.y * inv);
        acc.z = rn_tf32f(acc.z * inv);
        acc.w = rn_tf32f(acc.w * inv);
        out4[obase + r * per + j] = acc;
    }
}

// ---------------- tf32 mma.sync stacked GEMM (pre-rounded) + bias + relu ----------
// CTA: 128M x 256N, BK=32, 8 warps of 64x64. 3-stage cp.async pipeline (dist 2).
// grid.z = split-K factor: z covers K-range [kbeg, kend); gridDim.z>1 writes raw
// partial sums to g_part + z*NN*F (combined by k_combine).
// Logical A row n = [ g_AX[n, 0..4D) | H[n, 0..D) ], K = 5D, Kw = 4D. All pre-rounded.
// B = stacked pre-rounded [W|root], row-major [K, F].
#define AS_STRIDE 36
#define BS_STRIDE 264
#define ASZ (128 * AS_STRIDE)       // 4608 floats
#define BSZ (32 * BS_STRIDE)        // 8448 floats
#define NSTAGE 3
#define SM_TOTAL_B (NSTAGE * (ASZ + BSZ) * 4)   // 156672 bytes

__device__ __forceinline__ void cp_async16(unsigned dst, const float* src, int sz) {
    asm volatile("cp.async.ca.shared.global [%0], [%1], 16, %2;"
                 :: "r"(dst), "l"(src), "r"(sz));
}
__device__ __forceinline__ void cp_commit() {
    asm volatile("cp.async.commit_group;" ::: "memory");
}

__global__ __launch_bounds__(256)
void k_gemm_mma(const float* __restrict__ Bmat, const float* __restrict__ bias,
                const float* __restrict__ Hin,
                int M, int D, int F, int osel, int do_round, int kb1, int kb2) {
    extern __shared__ float sm[];
    const float* H = Hin;
    int K = 5 * D, Kw = 4 * D;

    int z = blockIdx.z, nz = gridDim.z;
    int kbeg = (z == 0) ? 0 : ((z == 1) ? kb1 : kb2);
    int kend = (z == nz - 1) ? K : ((z == 0) ? kb1 : kb2);
    bool partial = (nz > 1);
    float* out = partial ? (g_part + (size_t)z * NN * F)
                         : ((osel == 1) ? g_h1 : g_h2);

    int t = threadIdx.x, lane = t & 31, wid = t >> 5;
    int row0 = blockIdx.y * 128, col0 = blockIdx.x * 256;
    int m0w = (wid >> 2) * 64, n0w = (wid & 3) * 64;
    int g = lane >> 2, tg = lane & 3;
    int nch = (kend - kbeg) >> 5;

    float c[4][8][4];
#pragma unroll
    for (int i = 0; i < 4; i++)
#pragma unroll
        for (int j = 0; j < 8; j++)
#pragma unroll
            for (int k = 0; k < 4; k++) c[i][j][k] = 0.f;

    unsigned smb = (unsigned)__cvta_generic_to_shared(sm);

    auto load_chunk = [&](int ch, int buf) {
        unsigned as_b = smb + (unsigned)buf * ASZ * 4;
#pragma unroll
        for (int l = 0; l < 4; l++) {
            int id = t + (l << 8);
            int m = id >> 3, k4 = id & 7;
            int row = row0 + m;
            int krow = kbeg + (ch << 5) + (k4 << 2);
            const float* src = (krow < Kw) ? (g_AX + (size_t)row * Kw + krow)
                                           : (H + (size_t)row * D + (krow - Kw));
            cp_async16(as_b + (unsigned)(m * AS_STRIDE + k4 * 4) * 4, src, (row < M) ? 16 : 0);
        }
        unsigned bs_b = smb + (unsigned)(NSTAGE * ASZ + buf * BSZ) * 4;
#pragma unroll
        for (int l = 0; l < 8; l++) {
            int id = t + (l << 8);
            int k = id >> 6, n4 = id & 63;
            int krow = kbeg + (ch << 5) + k;
            int col = col0 + (n4 << 2);
            cp_async16(bs_b + (unsigned)(k * BS_STRIDE + n4 * 4) * 4,
                       Bmat + (size_t)krow * F + col, (col < F) ? 16 : 0);
        }
        cp_commit();
    };

    // prologue: fill 2 stages
    load_chunk(0, 0);
    if (nch > 1) load_chunk(1, 1);

    int buf = 0;
    for (int ch = 0; ch < nch; ch++) {
        if (ch + 2 < nch) load_chunk(ch + 2, (ch + 2) % NSTAGE);

        int rem = nch - 1 - ch;
        if (rem >= 2)      asm volatile("cp.async.wait_group 2;" ::: "memory");
        else if (rem == 1) asm volatile("cp.async.wait_group 1;" ::: "memory");
        else               asm volatile("cp.async.wait_group 0;" ::: "memory");
        __syncthreads();

        const float* As = sm + buf * ASZ;
        const float* Bs = sm + NSTAGE * ASZ + buf * BSZ;

#pragma unroll
        for (int kk = 0; kk < 32; kk += 8) {
            unsigned b[8][2];
#pragma unroll
            for (int nt = 0; nt < 8; nt++) {
                int n = n0w + nt * 8 + g;
                b[nt][0] = __float_as_uint(Bs[(kk + tg) * BS_STRIDE + n]);
                b[nt][1] = __float_as_uint(Bs[(kk + 4 + tg) * BS_STRIDE + n]);
            }
#pragma unroll
            for (int mt = 0; mt < 4; mt++) {
                int m = m0w + mt * 16 + g;
                unsigned a[4];
                a[0] = __float_as_uint(As[m * AS_STRIDE + kk + tg]);
                a[1] = __float_as_uint(As[(m + 8) * AS_STRIDE + kk + tg]);
                a[2] = __float_as_uint(As[m * AS_STRIDE + kk + 4 + tg]);
                a[3] = __float_as_uint(As[(m + 8) * AS_STRIDE + kk + 4 + tg]);
#pragma unroll
                for (int nt = 0; nt < 8; nt++)
                    asm volatile(
                        "mma.sync.aligned.m16n8k8.row.col.f32.tf32.tf32.f32 "
                        "{%0,%1,%2,%3},{%4,%5,%6,%7},{%8,%9},{%0,%1,%2,%3};"
                        : "+f"(c[mt][nt][0]), "+f"(c[mt][nt][1]),
                          "+f"(c[mt][nt][2]), "+f"(c[mt][nt][3])
                        : "r"(a[0]), "r"(a[1]), "r"(a[2]), "r"(a[3]),
                          "r"(b[nt][0]), "r"(b[nt][1]));
            }
        }
        __syncthreads();   // buffer-reuse guard
        buf = (buf + 1 == NSTAGE) ? 0 : buf + 1;
    }

    // ---- epilogue ----
    if (partial) {
        // raw partial sums, no bias/relu/round
#pragma unroll
        for (int mt = 0; mt < 4; mt++) {
            int r0 = row0 + m0w + mt * 16 + g;
#pragma unroll
            for (int nt = 0; nt < 8; nt++) {
                int cb = col0 + n0w + nt * 8 + tg * 2;
                if (cb < F) {
                    if (r0 < M)
                        *(float2*)(out + (size_t)r0 * F + cb) =
                            make_float2(c[mt][nt][0], c[mt][nt][1]);
                    if (r0 + 8 < M)
                        *(float2*)(out + (size_t)(r0 + 8) * F + cb) =
                            make_float2(c[mt][nt][2], c[mt][nt][3]);
                }
            }
        }
    } else {
#pragma unroll
        for (int mt = 0; mt < 4; mt++) {
            int r0 = row0 + m0w + mt * 16 + g;
#pragma unroll
            for (int nt = 0; nt < 8; nt++) {
                int cb = col0 + n0w + nt * 8 + tg * 2;
                if (cb < F) {
                    float b0 = bias[cb], b1 = bias[cb + 1];
                    float v0 = fmaxf(c[mt][nt][0] + b0, 0.f);
                    float v1 = fmaxf(c[mt][nt][1] + b1, 0.f);
                    float v2 = fmaxf(c[mt][nt][2] + b0, 0.f);
                    float v3 = fmaxf(c[mt][nt][3] + b1, 0.f);
                    if (do_round) {
                        v0 = rn_tf32f(v0); v1 = rn_tf32f(v1);
                        v2 = rn_tf32f(v2); v3 = rn_tf32f(v3);
                    }
                    if (r0 < M) *(float2*)(out + (size_t)r0 * F + cb) = make_float2(v0, v1);
                    if (r0 + 8 < M) *(float2*)(out + (size_t)(r0 + 8) * F + cb) = make_float2(v2, v3);
                }
            }
        }
    }
}

// ---------------- split-K combine: out = relu(sum(parts) + bias) (+round) -------
__global__ void k_combine(const float* __restrict__ bias, int F, int nsplit,
                          int osel, int do_round) {
    long i4 = (long)blockIdx.x * blockDim.x + threadIdx.x;
    long tot = (long)NN * F / 4;
    if (i4 >= tot) return;
    size_t s4 = (size_t)NN * F / 4;
    const float4* p = (const float4*)g_part;
    float4 a = p[i4];
    float4 b = p[s4 + i4];
    float4 s;
    s.x = a.x + b.x; s.y = a.y + b.y; s.z = a.z + b.z; s.w = a.w + b.w;
    if (nsplit == 3) {
        float4 cc = p[2 * s4 + i4];
        s.x += cc.x; s.y += cc.y; s.z += cc.z; s.w += cc.w;
    }
    int col4 = (int)(i4 % (F / 4));
    float4 bb = ((const float4*)bias)[col4];
    s.x = fmaxf(s.x + bb.x, 0.f);
    s.y = fmaxf(s.y + bb.y, 0.f);
    s.z = fmaxf(s.z + bb.z, 0.f);
    s.w = fmaxf(s.w + bb.w, 0.f);
    if (do_round) {
        s.x = rn_tf32f(s.x); s.y = rn_tf32f(s.y);
        s.z = rn_tf32f(s.z); s.w = rn_tf32f(s.w);
    }
    float* out = (osel == 1) ? g_h1 : g_h2;
    ((float4*)out)[i4] = s;
}

// ---------------- fused pool + MLP (batch is sorted -> contiguous node ranges) ----
__global__ void k_poolmlp(const int* __restrict__ batch,
                          const float* __restrict__ fw1, const float* __restrict__ fb1,
                          const float* __restrict__ fw2, const float* __restrict__ fb2,
                          float* __restrict__ out) {
    __shared__ float gbuf[F3];
    __shared__ float abuf[64];
    __shared__ int range[2];
    int g = blockIdx.x;
    int t = threadIdx.x;
    if (t < 2) {
        int key = g + t;
        int lo = 0, hi = NN;
        while (lo < hi) {
            int mid = (lo + hi) >> 1;
            if (batch[mid] < key) lo = mid + 1; else hi = mid;
        }
        range[t] = lo;
    }
    __syncthreads();
    int s = range[0], e = range[1];
    float invc = 1.f / fmaxf((float)(e - s), 1.f);
    for (int i = t; i < F3; i += 256) {
        float acc = 0.f;
        for (int n = s; n < e; n++) acc += g_h1[(size_t)n * F3 + i];
        gbuf[i] = acc * invc;
    }
    __syncthreads();
    if (t < 64) {
        float ssum = fb1[t];
        for (int k = 0; k < F3; k++) ssum += gbuf[k] * fw1[k * 64 + t];
        abuf[t] = fmaxf(ssum, 0.f);
    }
    __syncthreads();
    if (t == 0) {
        float o = fb2[0];
#pragma unroll
        for (int j = 0; j < 64; j++) o += abuf[j] * fw2[j];
        out[g] = o;
    }
}

// ---------------- launch ----------------
extern "C" void kernel_launch(void* const* d_in, const int* in_sizes, int n_in,
                              void* d_out, int out_size) {
    const float* x    = (const float*)d_in[0];
    const int*   ei   = (const int*)d_in[1];
    const int*   et   = (const int*)d_in[2];
    const int*   batch= (const int*)d_in[3];
    const float* W1   = (const float*)d_in[4];
    const float* r1   = (const float*)d_in[5];
    const float* b1   = (const float*)d_in[6];
    const float* W2   = (const float*)d_in[7];
    const float* r2   = (const float*)d_in[8];
    const float* b2   = (const float*)d_in[9];
    const float* W3   = (const float*)d_in[10];
    const float* r3   = (const float*)d_in[11];
    const float* b3   = (const float*)d_in[12];
    const float* fw1  = (const float*)d_in[13];
    const float* fb1  = (const float*)d_in[14];
    const float* fw2  = (const float*)d_in[15];
    const float* fb2  = (const float*)d_in[16];
    float* out = (float*)d_out;

    const int* srcI = ei;
    const int* dstI = ei + NE;

    cudaFuncSetAttribute(k_gemm_mma, cudaFuncAttributeMaxDynamicSharedMemorySize, SM_TOTAL_B);

    float *pB1, *pB2, *pB3, *pXr, *pH1, *pH2;
    cudaGetSymbolAddress((void**)&pB1, g_B1);
    cudaGetSymbolAddress((void**)&pB2, g_B2);
    cudaGetSymbolAddress((void**)&pB3, g_B3);
    cudaGetSymbolAddress((void**)&pXr, g_xr);
    cudaGetSymbolAddress((void**)&pH1, g_h1);
    cudaGetSymbolAddress((void**)&pH2, g_h2);

    // ---- weight / input pre-rounding (tf32) ----
    {
        long n1 = (long)320 * 1024;
        k_wconv<<<(int)((n1 / 4 + 255) / 256), 256>>>(W1, r1, pB1, (long)256 * 1024, n1);
        long n2 = (long)5120 * 1024;
        k_wconv<<<(int)((n2 / 4 + 255) / 256), 256>>>(W2, r2, pB2, (long)4096 * 1024, n2);
        long n3 = (long)5120 * 712;
        k_wconv<<<(int)((n3 / 4 + 255) / 256), 256>>>(W3, r3, pB3, (long)4096 * 712, n3);
        k_xconv<<<(NN * 64 / 4 + 255) / 256, 256>>>(x);
    }

    // ---- CSR build ----
    k_zero_cnt<<<(NBUCK + 255) / 256, 256>>>();
    k_count<<<(NE + 255) / 256, 256>>>(dstI, et);
    k_scanA<<<NSCANB, 256>>>();
    k_scanB<<<1, 256>>>();
    k_scanC<<<NSCANB, 256>>>();
    k_scatter<<<(NE + 255) / 256, 256>>>(srcI, dstI, et);

    // ---- layer 1: D=64 -> F=1024 (fused, no split) ----
    {
        const int D = 64, F = 1024;
        int per = D / 4, npb = 256 / per;
        k_aggcsr<<<(NN + npb - 1) / npb, 256>>>(pXr, 0, D);
        dim3 grid((F + 255) / 256, (NN + 127) / 128, 1);
        k_gemm_mma<<<grid, 256, SM_TOTAL_B>>>(pB1, b1, pXr, NN, D, F, 1, 1, 5 * D, 5 * D);
    }
    // ---- layer 2: D=1024 -> F=1024 (split-K x2) ----
    {
        const int D = 1024, F = 1024;
        k_aggcsr<<<NN, 256>>>(nullptr, 1, D);
        dim3 grid((F + 255) / 256, (NN + 127) / 128, 2);
        k_gemm_mma<<<grid, 256, SM_TOTAL_B>>>(pB2, b2, pH1, NN, D, F, 2, 1, 2560, 5120);
        long tot4 = (long)NN * F / 4;
        k_combine<<<(int)((tot4 + 255) / 256), 256>>>(b2, F, 2, 2, 1);
    }
    // ---- layer 3: D=1024 -> F=712 (split-K x3) ----
    {
        const int D = 1024, F = F3;
        k_aggcsr<<<NN, 256>>>(nullptr, 2, D);
        dim3 grid((F + 255) / 256, (NN + 127) / 128, 3);
        k_gemm_mma<<<grid, 256, SM_TOTAL_B>>>(pB3, b3, pH2, NN, D, F, 1, 0, 1728, 3456);
        long tot4 = (long)NN * F / 4;
        k_combine<<<(int)((tot4 + 255) / 256), 256>>>(b3, F, 3, 1, 0);
    }

    // ---- fused global mean pool + MLP ----
    k_poolmlp<<<NG, 256>>>(batch, fw1, fb1, fw2, fb2, out);
}